// round 11
// baseline (speedup 1.0000x reference)
#include <cuda_runtime.h>
#include <cuda_bf16.h>

// SmoothLDDTLoss — b=2, n=4096. Single fused kernel.
// IR=4 rows/thread (512x32 tiles), 1152 CTAs; launch_bounds(128,8) caps regs
// at 64 so 8 CTAs/SM -> 1184 capacity -> SINGLE WAVE (R10 ran 2 waves at 72
// regs / 7 CTAs/SM and paid a serialized 116-CTA tail).

#define NTOK 4096
#define TJ 32
#define TI 512
#define NTILES_B 576              // sum_{I=0}^{7} (128 - 16I)
#define TOTAL_CTAS (2 * NTILES_B)

#define TBL_N 512
#define TBL_H 0.03125f            // 16 / 512
#define DD_CLAMP 15.96875f        // 511 * H
#define MASK_BIG 2097152.0f       // 2^21 >> max cutoff^2 (900)

__device__ double g_acc[4];       // [num0, den0, num1, den1]
__device__ int g_done;

__device__ __forceinline__ float fsqrt_approx(float x) {
    float r; asm("sqrt.approx.f32 %0, %1;" : "=f"(r) : "f"(x)); return r;
}

// sum of 4 sigmoids sigma(t - x), t in {0.5,1,2,4}; rational: 1 exp + 1 div
__device__ __forceinline__ float sig4c(float x) {
    const float C0 = 0.60653066f, C1 = 0.36787944f, C2 = 0.13533528f, C3 = 0.018315639f;
    float e = __expf(x);
    float b0 = fmaf(e, C0, 1.0f), b1 = fmaf(e, C1, 1.0f);
    float b2 = fmaf(e, C2, 1.0f), b3 = fmaf(e, C3, 1.0f);
    float p01 = b0 * b1, p23 = b2 * b3;
    float numr = fmaf(b0 + b1, p23, (b2 + b3) * p01);
    return __fdividef(numr, p01 * p23);
}

struct RowS {
    float ax, ay, az, sp;   // -2*pred_i, |pred_i|^2
    float bx, by, bz, st;   // -2*true_i, |true_i|^2
    float nuc;              // 1 if nucleotide else 0
};

// one pair, dot-product form. A=(px,py,pz,|p|^2), B=(tx,ty,tz,|t|^2+maskbig), cj=675*wp_j
// NOTE: fminf clamp is load-bearing — it is also the NaN guard (sqrt.approx of a
// rounding-negative d2 yields NaN; fminf(NaN, CLAMP) returns CLAMP).
__device__ __forceinline__ void pair_dot(
    const RowS& r, float4 A, float4 B, float cj,
    const float2* __restrict__ tbl, float& num, float& den, bool active)
{
    float d2p = fmaf(r.ax, A.x, fmaf(r.ay, A.y, fmaf(r.az, A.z, r.sp))) + A.w;
    float d2t = fmaf(r.bx, B.x, fmaf(r.by, B.y, fmaf(r.bz, B.z, r.st))) + B.w;

    float cut2 = fmaf(r.nuc, cj, 225.0f);               // 225 or 900
    float mm = (d2t < cut2 && active) ? 1.0f : 0.0f;

    float dd = fminf(fabsf(fsqrt_approx(d2t) - fsqrt_approx(d2p)), DD_CLAMP);
    // byte offset = k*8, from magic FFMA (dd*256 integer part lands in mantissa)
    int boff = __float_as_int(fmaf(dd, 256.0f, 8388608.0f)) & 0xFF8;
    float2 e = *(const float2*)((const char*)tbl + boff);
    float v = fmaf(dd, e.y, e.x);                       // = 4 * eps

    num = fmaf(v, mm, num);
    den += mm;
}

__device__ __forceinline__ void load_row(
    const float* __restrict__ pred, const float* __restrict__ truec,
    const int* __restrict__ is_dna, const int* __restrict__ is_rna,
    int ig, RowS& r)
{
    float px = pred[3 * ig + 0], py = pred[3 * ig + 1], pz = pred[3 * ig + 2];
    float tx = truec[3 * ig + 0], ty = truec[3 * ig + 1], tz = truec[3 * ig + 2];
    r.ax = -2.0f * px; r.ay = -2.0f * py; r.az = -2.0f * pz;
    r.sp = fmaf(px, px, fmaf(py, py, pz * pz));
    r.bx = -2.0f * tx; r.by = -2.0f * ty; r.bz = -2.0f * tz;
    r.st = fmaf(tx, tx, fmaf(ty, ty, tz * tz));
    r.nuc = (is_dna[ig] != 0 || is_rna[ig] != 0) ? 1.0f : 0.0f;
}

__global__ void __launch_bounds__(128, 8)
lddt_fused(const float* __restrict__ pred,
           const float* __restrict__ truec,
           const int* __restrict__ is_dna,
           const int* __restrict__ is_rna,
           const int* __restrict__ cmask,
           float* __restrict__ out)
{
    // decode (batch, I, Jh): row I (8 rows of 512) has 128 - 16I j-tiles
    int lin = blockIdx.x;
    const int b = (lin >= NTILES_B) ? 1 : 0;
    lin -= b * NTILES_B;
    int I = 0;
    {
        int cnt = 128;
        while (lin >= cnt) { lin -= cnt; I++; cnt -= 16; }
    }
    const int Jh = 16 * I + lin;
    const bool hot = (lin >= 16);

    const int tid = threadIdx.x;

    __shared__ float2 tbl[TBL_N];      // (v_k - k*s_k, slope/H)
    __shared__ float vraw[TBL_N + 1];  // raw sig4 node values
    __shared__ float4 sA[TJ];          // pred xyz, |p|^2
    __shared__ float4 sB[TJ];          // true xyz, |t|^2 + (wt?0:BIG)
    __shared__ float  sC[TJ];          // 675 * wp_j

    for (int k = tid; k < TBL_N; k += 128)
        vraw[k] = sig4c((float)k * TBL_H);
    if (tid == 0) vraw[TBL_N] = sig4c(16.0f);

    const int base = b * NTOK;

    if (tid < TJ) {
        const int jg = base + Jh * TJ + tid;
        float px = pred[3 * jg + 0], py = pred[3 * jg + 1], pz = pred[3 * jg + 2];
        float tx = truec[3 * jg + 0], ty = truec[3 * jg + 1], tz = truec[3 * jg + 2];
        float np = fmaf(px, px, fmaf(py, py, pz * pz));
        float nt = fmaf(tx, tx, fmaf(ty, ty, tz * tz));
        bool wt = (cmask[jg] != 0);
        sA[tid] = make_float4(px, py, pz, np);
        sB[tid] = make_float4(tx, ty, tz, wt ? nt : nt + MASK_BIG);
        sC[tid] = (is_dna[jg] != 0 || is_rna[jg] != 0) ? 675.0f : 0.0f;
    }
    __syncthreads();

    // bake (base, slope/H) per bin
    for (int k = tid; k < TBL_N; k += 128) {
        float v0 = vraw[k];
        float s = vraw[k + 1] - v0;
        tbl[k] = make_float2(fmaf(-(float)k, s, v0), s * 32.0f);
    }

    // own 4 rows: tid, tid+128, tid+256, tid+384 within the 512-row i-tile
    const int ig0 = base + I * TI + tid;
    RowS r0, r1, r2, r3;
    load_row(pred, truec, is_dna, is_rna, ig0,       r0);
    load_row(pred, truec, is_dna, is_rna, ig0 + 128, r1);
    load_row(pred, truec, is_dna, is_rna, ig0 + 256, r2);
    load_row(pred, truec, is_dna, is_rna, ig0 + 384, r3);
    const float cm0 = (cmask[ig0]       != 0) ? 1.0f : 0.0f;
    const float cm1 = (cmask[ig0 + 128] != 0) ? 1.0f : 0.0f;
    const float cm2 = (cmask[ig0 + 256] != 0) ? 1.0f : 0.0f;
    const float cm3 = (cmask[ig0 + 384] != 0) ? 1.0f : 0.0f;

    __syncthreads();

    float n0 = 0.0f, d0 = 0.0f, n1 = 0.0f, d1 = 0.0f;
    float n2 = 0.0f, d2 = 0.0f, n3 = 0.0f, d3 = 0.0f;

    if (hot) {
        #pragma unroll 4
        for (int j = 0; j < TJ; ++j) {
            float4 A = sA[j];
            float4 B = sB[j];
            float cj = sC[j];
            pair_dot(r0, A, B, cj, tbl, n0, d0, true);
            pair_dot(r1, A, B, cj, tbl, n1, d1, true);
            pair_dot(r2, A, B, cj, tbl, n2, d2, true);
            pair_dot(r3, A, B, cj, tbl, n3, d3, true);
        }
    } else {
        const int i0 = I * TI + tid;
        const int jbase = Jh * TJ;
        #pragma unroll 2
        for (int j = 0; j < TJ; ++j) {
            float4 A = sA[j];
            float4 B = sB[j];
            float cj = sC[j];
            const int jcol = jbase + j;
            pair_dot(r0, A, B, cj, tbl, n0, d0, jcol > i0);
            pair_dot(r1, A, B, cj, tbl, n1, d1, jcol > i0 + 128);
            pair_dot(r2, A, B, cj, tbl, n2, d2, jcol > i0 + 256);
            pair_dot(r3, A, B, cj, tbl, n3, d3, jcol > i0 + 384);
        }
    }

    float acc_num = fmaf(n0, cm0, n1 * cm1) + fmaf(n2, cm2, n3 * cm3);
    float acc_den = fmaf(d0, cm0, d1 * cm1) + fmaf(d2, cm2, d3 * cm3);

    #pragma unroll
    for (int o = 16; o > 0; o >>= 1) {
        acc_num += __shfl_xor_sync(0xFFFFFFFFu, acc_num, o);
        acc_den += __shfl_xor_sync(0xFFFFFFFFu, acc_den, o);
    }
    __shared__ float rn[4], rd[4];
    const int wid = tid >> 5;
    if ((tid & 31) == 0) { rn[wid] = acc_num; rd[wid] = acc_den; }
    __syncthreads();

    if (tid == 0) {
        float tn = rn[0] + rn[1] + rn[2] + rn[3];
        float td = rd[0] + rd[1] + rd[2] + rd[3];
        atomicAdd(&g_acc[2 * b + 0], (double)tn);
        atomicAdd(&g_acc[2 * b + 1], (double)td);
        __threadfence();
        int done = atomicAdd(&g_done, 1);
        if (done == TOTAL_CTAS - 1) {
            volatile double* acc = g_acc;
            double num0 = acc[0], den0 = acc[1], num1 = acc[2], den1 = acc[3];
            double e0 = 2.0 * den0; if (e0 < 1.0) e0 = 1.0;
            double e1 = 2.0 * den1; if (e1 < 1.0) e1 = 1.0;
            double l0 = (0.5 * num0) / e0;   // 2 * 0.25 * num / (2*den)
            double l1 = (0.5 * num1) / e1;
            out[0] = (float)(1.0 - 0.5 * (l0 + l1));
            acc[0] = 0.0; acc[1] = 0.0; acc[2] = 0.0; acc[3] = 0.0;
            g_done = 0;
            __threadfence();
        }
    }
}

extern "C" void kernel_launch(void* const* d_in, const int* in_sizes, int n_in,
                              void* d_out, int out_size) {
    const float* pred  = (const float*)d_in[0];
    const float* truec = (const float*)d_in[1];
    const int*   dna   = (const int*)d_in[2];
    const int*   rna   = (const int*)d_in[3];
    const int*   cm    = (const int*)d_in[4];

    lddt_fused<<<TOTAL_CTAS, 128>>>(pred, truec, dna, rna, cm, (float*)d_out);
}

// round 12
// speedup vs baseline: 1.0707x; 1.0707x over previous
#include <cuda_runtime.h>
#include <cuda_bf16.h>

// SmoothLDDTLoss — b=2, n=4096. Single fused kernel.
// R7 arithmetic (dot-product distances, select mask, interp baked LUT),
// 256-thread CTAs over 512x32 tiles with IR=2 rows/thread (same warp math,
// half the per-CTA fixed overhead), byte-offset magic LUT index.

#define NTOK 4096
#define TJ 32
#define TI 512
#define BLK 256
#define NTILES_B 576              // sum_{I=0}^{7} (128 - 16I)
#define TOTAL_CTAS (2 * NTILES_B)

#define TBL_N 512
#define TBL_H 0.03125f            // 16 / 512
#define DD_CLAMP 15.96875f        // 511 * H
#define MASK_BIG 2097152.0f       // 2^21 >> max cutoff^2 (900)

__device__ double g_acc[4];       // [num0, den0, num1, den1]
__device__ int g_done;

__device__ __forceinline__ float fsqrt_approx(float x) {
    float r; asm("sqrt.approx.f32 %0, %1;" : "=f"(r) : "f"(x)); return r;
}

// sum of 4 sigmoids sigma(t - x), t in {0.5,1,2,4}; rational: 1 exp + 1 div
__device__ __forceinline__ float sig4c(float x) {
    const float C0 = 0.60653066f, C1 = 0.36787944f, C2 = 0.13533528f, C3 = 0.018315639f;
    float e = __expf(x);
    float b0 = fmaf(e, C0, 1.0f), b1 = fmaf(e, C1, 1.0f);
    float b2 = fmaf(e, C2, 1.0f), b3 = fmaf(e, C3, 1.0f);
    float p01 = b0 * b1, p23 = b2 * b3;
    float numr = fmaf(b0 + b1, p23, (b2 + b3) * p01);
    return __fdividef(numr, p01 * p23);
}

struct RowS {
    float ax, ay, az, sp;   // -2*pred_i, |pred_i|^2
    float bx, by, bz, st;   // -2*true_i, |true_i|^2
    float nuc;              // 1 if nucleotide else 0
};

// one pair, dot-product form. A=(px,py,pz,|p|^2), B=(tx,ty,tz,|t|^2+maskbig), cj=675*wp_j
// NOTE: fminf clamp doubles as NaN guard (fminf(NaN, C) -> C).
__device__ __forceinline__ void pair_dot(
    const RowS& r, float4 A, float4 B, float cj,
    const float2* __restrict__ tbl, float& num, float& den, bool active)
{
    float d2p = fmaf(r.ax, A.x, fmaf(r.ay, A.y, fmaf(r.az, A.z, r.sp))) + A.w;
    float d2t = fmaf(r.bx, B.x, fmaf(r.by, B.y, fmaf(r.bz, B.z, r.st))) + B.w;

    float cut2 = fmaf(r.nuc, cj, 225.0f);               // 225 or 900
    float mm = (d2t < cut2 && active) ? 1.0f : 0.0f;

    float dd = fminf(fabsf(fsqrt_approx(d2t) - fsqrt_approx(d2p)), DD_CLAMP);
    // direct float2 byte offset: int(dd*256) & ~7 == bin*8
    int boff = __float_as_int(fmaf(dd, 256.0f, 8388608.0f)) & 0xFF8;
    float2 e = *(const float2*)((const char*)tbl + boff);
    float v = fmaf(dd, e.y, e.x);                       // = 4 * eps

    num = fmaf(v, mm, num);
    den += mm;
}

__global__ void __launch_bounds__(BLK)
lddt_fused(const float* __restrict__ pred,
           const float* __restrict__ truec,
           const int* __restrict__ is_dna,
           const int* __restrict__ is_rna,
           const int* __restrict__ cmask,
           float* __restrict__ out)
{
    // decode (batch, I, Jh): i-row I (8 rows of 512) has 128 - 16I j-tiles
    int lin = blockIdx.x;
    const int b = (lin >= NTILES_B) ? 1 : 0;
    lin -= b * NTILES_B;
    int I = 0;
    {
        int cnt = 128;
        while (lin >= cnt) { lin -= cnt; I++; cnt -= 16; }
    }
    const int Jh = 16 * I + lin;
    const bool hot = (lin >= 16);      // j-tile entirely above both row groups

    const int tid = threadIdx.x;

    __shared__ float2 tbl[TBL_N];      // (v_k - k*s_k, 32*s_k)
    __shared__ float vraw[TBL_N + 1];  // raw sig4 node values
    __shared__ float4 sA[TJ];          // pred xyz, |p|^2
    __shared__ float4 sB[TJ];          // true xyz, |t|^2 + (wt?0:BIG)
    __shared__ float  sC[TJ];          // 675 * wp_j

    for (int k = tid; k < TBL_N; k += BLK)
        vraw[k] = sig4c((float)k * TBL_H);
    if (tid == 0) vraw[TBL_N] = sig4c(16.0f);

    const int base = b * NTOK;

    if (tid < TJ) {
        const int jg = base + Jh * TJ + tid;
        float px = pred[3 * jg + 0], py = pred[3 * jg + 1], pz = pred[3 * jg + 2];
        float tx = truec[3 * jg + 0], ty = truec[3 * jg + 1], tz = truec[3 * jg + 2];
        float np = fmaf(px, px, fmaf(py, py, pz * pz));
        float nt = fmaf(tx, tx, fmaf(ty, ty, tz * tz));
        bool wt = (cmask[jg] != 0);
        sA[tid] = make_float4(px, py, pz, np);
        sB[tid] = make_float4(tx, ty, tz, wt ? nt : nt + MASK_BIG);
        sC[tid] = (is_dna[jg] != 0 || is_rna[jg] != 0) ? 675.0f : 0.0f;
    }
    __syncthreads();

    // bake (base, slope*32) per bin
    for (int k = tid; k < TBL_N; k += BLK) {
        float v0 = vraw[k];
        float s = vraw[k + 1] - v0;
        tbl[k] = make_float2(fmaf(-(float)k, s, v0), s * 32.0f);
    }

    // own rows: r0 = 512*I + tid, r1 = r0 + 256
    const int ig0 = base + I * TI + tid;
    const int ig1 = ig0 + BLK;
    RowS r0, r1;
    {
        float px = pred[3 * ig0 + 0], py = pred[3 * ig0 + 1], pz = pred[3 * ig0 + 2];
        float tx = truec[3 * ig0 + 0], ty = truec[3 * ig0 + 1], tz = truec[3 * ig0 + 2];
        r0.ax = -2.0f * px; r0.ay = -2.0f * py; r0.az = -2.0f * pz;
        r0.sp = fmaf(px, px, fmaf(py, py, pz * pz));
        r0.bx = -2.0f * tx; r0.by = -2.0f * ty; r0.bz = -2.0f * tz;
        r0.st = fmaf(tx, tx, fmaf(ty, ty, tz * tz));
        r0.nuc = (is_dna[ig0] != 0 || is_rna[ig0] != 0) ? 1.0f : 0.0f;
    }
    {
        float px = pred[3 * ig1 + 0], py = pred[3 * ig1 + 1], pz = pred[3 * ig1 + 2];
        float tx = truec[3 * ig1 + 0], ty = truec[3 * ig1 + 1], tz = truec[3 * ig1 + 2];
        r1.ax = -2.0f * px; r1.ay = -2.0f * py; r1.az = -2.0f * pz;
        r1.sp = fmaf(px, px, fmaf(py, py, pz * pz));
        r1.bx = -2.0f * tx; r1.by = -2.0f * ty; r1.bz = -2.0f * tz;
        r1.st = fmaf(tx, tx, fmaf(ty, ty, tz * tz));
        r1.nuc = (is_dna[ig1] != 0 || is_rna[ig1] != 0) ? 1.0f : 0.0f;
    }
    const float cm0 = (cmask[ig0] != 0) ? 1.0f : 0.0f;
    const float cm1 = (cmask[ig1] != 0) ? 1.0f : 0.0f;

    __syncthreads();

    float n0 = 0.0f, d0 = 0.0f, n1 = 0.0f, d1 = 0.0f;

    if (hot) {
        #pragma unroll 4
        for (int j = 0; j < TJ; ++j) {
            float4 A = sA[j];
            float4 B = sB[j];
            float cj = sC[j];
            pair_dot(r0, A, B, cj, tbl, n0, d0, true);
            pair_dot(r1, A, B, cj, tbl, n1, d1, true);
        }
    } else {
        const int i0 = I * TI + tid;
        const int i1 = i0 + BLK;
        const int jbase = Jh * TJ;
        #pragma unroll 4
        for (int j = 0; j < TJ; ++j) {
            float4 A = sA[j];
            float4 B = sB[j];
            float cj = sC[j];
            const int jcol = jbase + j;
            pair_dot(r0, A, B, cj, tbl, n0, d0, jcol > i0);
            pair_dot(r1, A, B, cj, tbl, n1, d1, jcol > i1);
        }
    }

    float acc_num = fmaf(n0, cm0, n1 * cm1);
    float acc_den = fmaf(d0, cm0, d1 * cm1);

    #pragma unroll
    for (int o = 16; o > 0; o >>= 1) {
        acc_num += __shfl_xor_sync(0xFFFFFFFFu, acc_num, o);
        acc_den += __shfl_xor_sync(0xFFFFFFFFu, acc_den, o);
    }
    __shared__ float rn[BLK / 32], rd[BLK / 32];
    const int wid = tid >> 5;
    if ((tid & 31) == 0) { rn[wid] = acc_num; rd[wid] = acc_den; }
    __syncthreads();

    if (tid == 0) {
        float tn = 0.0f, td = 0.0f;
        #pragma unroll
        for (int w = 0; w < BLK / 32; ++w) { tn += rn[w]; td += rd[w]; }
        atomicAdd(&g_acc[2 * b + 0], (double)tn);
        atomicAdd(&g_acc[2 * b + 1], (double)td);
        __threadfence();
        int done = atomicAdd(&g_done, 1);
        if (done == TOTAL_CTAS - 1) {
            volatile double* acc = g_acc;
            double num0 = acc[0], den0 = acc[1], num1 = acc[2], den1 = acc[3];
            double e0 = 2.0 * den0; if (e0 < 1.0) e0 = 1.0;
            double e1 = 2.0 * den1; if (e1 < 1.0) e1 = 1.0;
            double l0 = (0.5 * num0) / e0;   // 2 * 0.25 * num / (2*den)
            double l1 = (0.5 * num1) / e1;
            out[0] = (float)(1.0 - 0.5 * (l0 + l1));
            acc[0] = 0.0; acc[1] = 0.0; acc[2] = 0.0; acc[3] = 0.0;
            g_done = 0;
            __threadfence();
        }
    }
}

extern "C" void kernel_launch(void* const* d_in, const int* in_sizes, int n_in,
                              void* d_out, int out_size) {
    const float* pred  = (const float*)d_in[0];
    const float* truec = (const float*)d_in[1];
    const int*   dna   = (const int*)d_in[2];
    const int*   rna   = (const int*)d_in[3];
    const int*   cm    = (const int*)d_in[4];

    lddt_fused<<<TOTAL_CTAS, BLK>>>(pred, truec, dna, rna, cm, (float*)d_out);
}

// round 13
// speedup vs baseline: 1.1604x; 1.0837x over previous
#include <cuda_runtime.h>
#include <cuda_bf16.h>

// SmoothLDDTLoss — b=2, n=4096. Single fused kernel.
// R12 arithmetic (dot-product distances, select mask, byte-offset baked LUT)
// at R7 shape: BLK=128, 256x32 tiles, IR=2, 2176 CTAs. LUT 256 bins.

#define NTOK 4096
#define TJ 32
#define TI 256
#define BLK 128
#define NTILES_B 1088             // sum_{I=0}^{15} (128 - 8I)
#define TOTAL_CTAS (2 * NTILES_B)

#define TBL_N 256
#define TBL_H 0.0625f             // 16 / 256
#define DD_CLAMP 15.9375f         // 255 * H
#define MASK_BIG 2097152.0f       // 2^21 >> max cutoff^2 (900)

__device__ double g_acc[4];       // [num0, den0, num1, den1]
__device__ int g_done;

__device__ __forceinline__ float fsqrt_approx(float x) {
    float r; asm("sqrt.approx.f32 %0, %1;" : "=f"(r) : "f"(x)); return r;
}

// sum of 4 sigmoids sigma(t - x), t in {0.5,1,2,4}; rational: 1 exp + 1 div
__device__ __forceinline__ float sig4c(float x) {
    const float C0 = 0.60653066f, C1 = 0.36787944f, C2 = 0.13533528f, C3 = 0.018315639f;
    float e = __expf(x);
    float b0 = fmaf(e, C0, 1.0f), b1 = fmaf(e, C1, 1.0f);
    float b2 = fmaf(e, C2, 1.0f), b3 = fmaf(e, C3, 1.0f);
    float p01 = b0 * b1, p23 = b2 * b3;
    float numr = fmaf(b0 + b1, p23, (b2 + b3) * p01);
    return __fdividef(numr, p01 * p23);
}

struct RowS {
    float ax, ay, az, sp;   // -2*pred_i, |pred_i|^2
    float bx, by, bz, st;   // -2*true_i, |true_i|^2
    float nuc;              // 1 if nucleotide else 0
};

// one pair, dot-product form. A=(px,py,pz,|p|^2), B=(tx,ty,tz,|t|^2+maskbig), cj=675*wp_j
// NOTE: fminf clamp doubles as NaN guard (fminf(NaN, C) -> C).
__device__ __forceinline__ void pair_dot(
    const RowS& r, float4 A, float4 B, float cj,
    const float2* __restrict__ tbl, float& num, float& den, bool active)
{
    float d2p = fmaf(r.ax, A.x, fmaf(r.ay, A.y, fmaf(r.az, A.z, r.sp))) + A.w;
    float d2t = fmaf(r.bx, B.x, fmaf(r.by, B.y, fmaf(r.bz, B.z, r.st))) + B.w;

    float cut2 = fmaf(r.nuc, cj, 225.0f);               // 225 or 900
    float mm = (d2t < cut2 && active) ? 1.0f : 0.0f;

    float dd = fminf(fabsf(fsqrt_approx(d2t) - fsqrt_approx(d2p)), DD_CLAMP);
    // direct float2 byte offset: (int(dd*16) & 255) * 8, via magic FFMA
    int boff = __float_as_int(fmaf(dd, 128.0f, 8388608.0f)) & 0x7F8;
    float2 e = *(const float2*)((const char*)tbl + boff);
    float v = fmaf(dd, e.y, e.x);                       // = 4 * eps

    num = fmaf(v, mm, num);
    den += mm;
}

__global__ void __launch_bounds__(BLK)
lddt_fused(const float* __restrict__ pred,
           const float* __restrict__ truec,
           const int* __restrict__ is_dna,
           const int* __restrict__ is_rna,
           const int* __restrict__ cmask,
           float* __restrict__ out)
{
    // decode (batch, I, Jh): i-row I (16 rows of 256) has 128 - 8I j-tiles
    int lin = blockIdx.x;
    const int b = (lin >= NTILES_B) ? 1 : 0;
    lin -= b * NTILES_B;
    int I = 0;
    {
        int cnt = 128;
        while (lin >= cnt) { lin -= cnt; I++; cnt -= 8; }
    }
    const int Jh = 8 * I + lin;
    const bool hot = (lin >= 8);

    const int tid = threadIdx.x;

    __shared__ float2 tbl[TBL_N];      // (v_k - k*s_k, s_k/H)
    __shared__ float vraw[TBL_N + 1];  // raw sig4 node values
    __shared__ float4 sA[TJ];          // pred xyz, |p|^2
    __shared__ float4 sB[TJ];          // true xyz, |t|^2 + (wt?0:BIG)
    __shared__ float  sC[TJ];          // 675 * wp_j

    for (int k = tid; k < TBL_N; k += BLK)
        vraw[k] = sig4c((float)k * TBL_H);
    if (tid == 0) vraw[TBL_N] = sig4c(16.0f);

    const int base = b * NTOK;

    if (tid < TJ) {
        const int jg = base + Jh * TJ + tid;
        float px = pred[3 * jg + 0], py = pred[3 * jg + 1], pz = pred[3 * jg + 2];
        float tx = truec[3 * jg + 0], ty = truec[3 * jg + 1], tz = truec[3 * jg + 2];
        float np = fmaf(px, px, fmaf(py, py, pz * pz));
        float nt = fmaf(tx, tx, fmaf(ty, ty, tz * tz));
        bool wt = (cmask[jg] != 0);
        sA[tid] = make_float4(px, py, pz, np);
        sB[tid] = make_float4(tx, ty, tz, wt ? nt : nt + MASK_BIG);
        sC[tid] = (is_dna[jg] != 0 || is_rna[jg] != 0) ? 675.0f : 0.0f;
    }
    __syncthreads();

    // bake (base, slope/H) per bin
    for (int k = tid; k < TBL_N; k += BLK) {
        float v0 = vraw[k];
        float s = vraw[k + 1] - v0;
        tbl[k] = make_float2(fmaf(-(float)k, s, v0), s * 16.0f);
    }

    // own rows: r0 = 256*I + tid, r1 = r0 + 128
    const int ig0 = base + I * TI + tid;
    const int ig1 = ig0 + BLK;
    RowS r0, r1;
    {
        float px = pred[3 * ig0 + 0], py = pred[3 * ig0 + 1], pz = pred[3 * ig0 + 2];
        float tx = truec[3 * ig0 + 0], ty = truec[3 * ig0 + 1], tz = truec[3 * ig0 + 2];
        r0.ax = -2.0f * px; r0.ay = -2.0f * py; r0.az = -2.0f * pz;
        r0.sp = fmaf(px, px, fmaf(py, py, pz * pz));
        r0.bx = -2.0f * tx; r0.by = -2.0f * ty; r0.bz = -2.0f * tz;
        r0.st = fmaf(tx, tx, fmaf(ty, ty, tz * tz));
        r0.nuc = (is_dna[ig0] != 0 || is_rna[ig0] != 0) ? 1.0f : 0.0f;
    }
    {
        float px = pred[3 * ig1 + 0], py = pred[3 * ig1 + 1], pz = pred[3 * ig1 + 2];
        float tx = truec[3 * ig1 + 0], ty = truec[3 * ig1 + 1], tz = truec[3 * ig1 + 2];
        r1.ax = -2.0f * px; r1.ay = -2.0f * py; r1.az = -2.0f * pz;
        r1.sp = fmaf(px, px, fmaf(py, py, pz * pz));
        r1.bx = -2.0f * tx; r1.by = -2.0f * ty; r1.bz = -2.0f * tz;
        r1.st = fmaf(tx, tx, fmaf(ty, ty, tz * tz));
        r1.nuc = (is_dna[ig1] != 0 || is_rna[ig1] != 0) ? 1.0f : 0.0f;
    }
    const float cm0 = (cmask[ig0] != 0) ? 1.0f : 0.0f;
    const float cm1 = (cmask[ig1] != 0) ? 1.0f : 0.0f;

    __syncthreads();

    float n0 = 0.0f, d0 = 0.0f, n1 = 0.0f, d1 = 0.0f;

    if (hot) {
        #pragma unroll 4
        for (int j = 0; j < TJ; ++j) {
            float4 A = sA[j];
            float4 B = sB[j];
            float cj = sC[j];
            pair_dot(r0, A, B, cj, tbl, n0, d0, true);
            pair_dot(r1, A, B, cj, tbl, n1, d1, true);
        }
    } else {
        const int i0 = I * TI + tid;
        const int i1 = i0 + BLK;
        const int jbase = Jh * TJ;
        #pragma unroll 4
        for (int j = 0; j < TJ; ++j) {
            float4 A = sA[j];
            float4 B = sB[j];
            float cj = sC[j];
            const int jcol = jbase + j;
            pair_dot(r0, A, B, cj, tbl, n0, d0, jcol > i0);
            pair_dot(r1, A, B, cj, tbl, n1, d1, jcol > i1);
        }
    }

    float acc_num = fmaf(n0, cm0, n1 * cm1);
    float acc_den = fmaf(d0, cm0, d1 * cm1);

    #pragma unroll
    for (int o = 16; o > 0; o >>= 1) {
        acc_num += __shfl_xor_sync(0xFFFFFFFFu, acc_num, o);
        acc_den += __shfl_xor_sync(0xFFFFFFFFu, acc_den, o);
    }
    __shared__ float rn[BLK / 32], rd[BLK / 32];
    const int wid = tid >> 5;
    if ((tid & 31) == 0) { rn[wid] = acc_num; rd[wid] = acc_den; }
    __syncthreads();

    if (tid == 0) {
        float tn = rn[0] + rn[1] + rn[2] + rn[3];
        float td = rd[0] + rd[1] + rd[2] + rd[3];
        atomicAdd(&g_acc[2 * b + 0], (double)tn);
        atomicAdd(&g_acc[2 * b + 1], (double)td);
        __threadfence();
        int done = atomicAdd(&g_done, 1);
        if (done == TOTAL_CTAS - 1) {
            volatile double* acc = g_acc;
            double num0 = acc[0], den0 = acc[1], num1 = acc[2], den1 = acc[3];
            double e0 = 2.0 * den0; if (e0 < 1.0) e0 = 1.0;
            double e1 = 2.0 * den1; if (e1 < 1.0) e1 = 1.0;
            double l0 = (0.5 * num0) / e0;   // 2 * 0.25 * num / (2*den)
            double l1 = (0.5 * num1) / e1;
            out[0] = (float)(1.0 - 0.5 * (l0 + l1));
            acc[0] = 0.0; acc[1] = 0.0; acc[2] = 0.0; acc[3] = 0.0;
            g_done = 0;
            __threadfence();
        }
    }
}

extern "C" void kernel_launch(void* const* d_in, const int* in_sizes, int n_in,
                              void* d_out, int out_size) {
    const float* pred  = (const float*)d_in[0];
    const float* truec = (const float*)d_in[1];
    const int*   dna   = (const int*)d_in[2];
    const int*   rna   = (const int*)d_in[3];
    const int*   cm    = (const int*)d_in[4];

    lddt_fused<<<TOTAL_CTAS, BLK>>>(pred, truec, dna, rna, cm, (float*)d_out);
}

// round 14
// speedup vs baseline: 1.1631x; 1.0024x over previous
#include <cuda_runtime.h>
#include <cuda_bf16.h>

// SmoothLDDTLoss — b=2, n=4096. Single fused kernel.
// R13 (dot-product distances, select mask, byte-offset baked 256-bin LUT,
// BLK=128, 256x32 tiles, IR=2, 2176 CTAs) with hot-loop unroll 8.

#define NTOK 4096
#define TJ 32
#define TI 256
#define BLK 128
#define NTILES_B 1088             // sum_{I=0}^{15} (128 - 8I)
#define TOTAL_CTAS (2 * NTILES_B)

#define TBL_N 256
#define TBL_H 0.0625f             // 16 / 256
#define DD_CLAMP 15.9375f         // 255 * H
#define MASK_BIG 2097152.0f       // 2^21 >> max cutoff^2 (900)

__device__ double g_acc[4];       // [num0, den0, num1, den1]
__device__ int g_done;

__device__ __forceinline__ float fsqrt_approx(float x) {
    float r; asm("sqrt.approx.f32 %0, %1;" : "=f"(r) : "f"(x)); return r;
}

// sum of 4 sigmoids sigma(t - x), t in {0.5,1,2,4}; rational: 1 exp + 1 div
__device__ __forceinline__ float sig4c(float x) {
    const float C0 = 0.60653066f, C1 = 0.36787944f, C2 = 0.13533528f, C3 = 0.018315639f;
    float e = __expf(x);
    float b0 = fmaf(e, C0, 1.0f), b1 = fmaf(e, C1, 1.0f);
    float b2 = fmaf(e, C2, 1.0f), b3 = fmaf(e, C3, 1.0f);
    float p01 = b0 * b1, p23 = b2 * b3;
    float numr = fmaf(b0 + b1, p23, (b2 + b3) * p01);
    return __fdividef(numr, p01 * p23);
}

struct RowS {
    float ax, ay, az, sp;   // -2*pred_i, |pred_i|^2
    float bx, by, bz, st;   // -2*true_i, |true_i|^2
    float nuc;              // 1 if nucleotide else 0
};

// one pair, dot-product form. A=(px,py,pz,|p|^2), B=(tx,ty,tz,|t|^2+maskbig), cj=675*wp_j
// NOTE: fminf clamp doubles as NaN guard (fminf(NaN, C) -> C).
__device__ __forceinline__ void pair_dot(
    const RowS& r, float4 A, float4 B, float cj,
    const float2* __restrict__ tbl, float& num, float& den, bool active)
{
    float d2p = fmaf(r.ax, A.x, fmaf(r.ay, A.y, fmaf(r.az, A.z, r.sp))) + A.w;
    float d2t = fmaf(r.bx, B.x, fmaf(r.by, B.y, fmaf(r.bz, B.z, r.st))) + B.w;

    float cut2 = fmaf(r.nuc, cj, 225.0f);               // 225 or 900
    float mm = (d2t < cut2 && active) ? 1.0f : 0.0f;

    float dd = fminf(fabsf(fsqrt_approx(d2t) - fsqrt_approx(d2p)), DD_CLAMP);
    // direct float2 byte offset: (int(dd*16) & 255) * 8, via magic FFMA
    int boff = __float_as_int(fmaf(dd, 128.0f, 8388608.0f)) & 0x7F8;
    float2 e = *(const float2*)((const char*)tbl + boff);
    float v = fmaf(dd, e.y, e.x);                       // = 4 * eps

    num = fmaf(v, mm, num);
    den += mm;
}

__global__ void __launch_bounds__(BLK)
lddt_fused(const float* __restrict__ pred,
           const float* __restrict__ truec,
           const int* __restrict__ is_dna,
           const int* __restrict__ is_rna,
           const int* __restrict__ cmask,
           float* __restrict__ out)
{
    // decode (batch, I, Jh): i-row I (16 rows of 256) has 128 - 8I j-tiles
    int lin = blockIdx.x;
    const int b = (lin >= NTILES_B) ? 1 : 0;
    lin -= b * NTILES_B;
    int I = 0;
    {
        int cnt = 128;
        while (lin >= cnt) { lin -= cnt; I++; cnt -= 8; }
    }
    const int Jh = 8 * I + lin;
    const bool hot = (lin >= 8);

    const int tid = threadIdx.x;

    __shared__ float2 tbl[TBL_N];      // (v_k - k*s_k, s_k/H)
    __shared__ float vraw[TBL_N + 1];  // raw sig4 node values
    __shared__ float4 sA[TJ];          // pred xyz, |p|^2
    __shared__ float4 sB[TJ];          // true xyz, |t|^2 + (wt?0:BIG)
    __shared__ float  sC[TJ];          // 675 * wp_j

    for (int k = tid; k < TBL_N; k += BLK)
        vraw[k] = sig4c((float)k * TBL_H);
    if (tid == 0) vraw[TBL_N] = sig4c(16.0f);

    const int base = b * NTOK;

    if (tid < TJ) {
        const int jg = base + Jh * TJ + tid;
        float px = pred[3 * jg + 0], py = pred[3 * jg + 1], pz = pred[3 * jg + 2];
        float tx = truec[3 * jg + 0], ty = truec[3 * jg + 1], tz = truec[3 * jg + 2];
        float np = fmaf(px, px, fmaf(py, py, pz * pz));
        float nt = fmaf(tx, tx, fmaf(ty, ty, tz * tz));
        bool wt = (cmask[jg] != 0);
        sA[tid] = make_float4(px, py, pz, np);
        sB[tid] = make_float4(tx, ty, tz, wt ? nt : nt + MASK_BIG);
        sC[tid] = (is_dna[jg] != 0 || is_rna[jg] != 0) ? 675.0f : 0.0f;
    }
    __syncthreads();

    // bake (base, slope/H) per bin
    for (int k = tid; k < TBL_N; k += BLK) {
        float v0 = vraw[k];
        float s = vraw[k + 1] - v0;
        tbl[k] = make_float2(fmaf(-(float)k, s, v0), s * 16.0f);
    }

    // own rows: r0 = 256*I + tid, r1 = r0 + 128
    const int ig0 = base + I * TI + tid;
    const int ig1 = ig0 + BLK;
    RowS r0, r1;
    {
        float px = pred[3 * ig0 + 0], py = pred[3 * ig0 + 1], pz = pred[3 * ig0 + 2];
        float tx = truec[3 * ig0 + 0], ty = truec[3 * ig0 + 1], tz = truec[3 * ig0 + 2];
        r0.ax = -2.0f * px; r0.ay = -2.0f * py; r0.az = -2.0f * pz;
        r0.sp = fmaf(px, px, fmaf(py, py, pz * pz));
        r0.bx = -2.0f * tx; r0.by = -2.0f * ty; r0.bz = -2.0f * tz;
        r0.st = fmaf(tx, tx, fmaf(ty, ty, tz * tz));
        r0.nuc = (is_dna[ig0] != 0 || is_rna[ig0] != 0) ? 1.0f : 0.0f;
    }
    {
        float px = pred[3 * ig1 + 0], py = pred[3 * ig1 + 1], pz = pred[3 * ig1 + 2];
        float tx = truec[3 * ig1 + 0], ty = truec[3 * ig1 + 1], tz = truec[3 * ig1 + 2];
        r1.ax = -2.0f * px; r1.ay = -2.0f * py; r1.az = -2.0f * pz;
        r1.sp = fmaf(px, px, fmaf(py, py, pz * pz));
        r1.bx = -2.0f * tx; r1.by = -2.0f * ty; r1.bz = -2.0f * tz;
        r1.st = fmaf(tx, tx, fmaf(ty, ty, tz * tz));
        r1.nuc = (is_dna[ig1] != 0 || is_rna[ig1] != 0) ? 1.0f : 0.0f;
    }
    const float cm0 = (cmask[ig0] != 0) ? 1.0f : 0.0f;
    const float cm1 = (cmask[ig1] != 0) ? 1.0f : 0.0f;

    __syncthreads();

    float n0 = 0.0f, d0 = 0.0f, n1 = 0.0f, d1 = 0.0f;

    if (hot) {
        #pragma unroll 8
        for (int j = 0; j < TJ; ++j) {
            float4 A = sA[j];
            float4 B = sB[j];
            float cj = sC[j];
            pair_dot(r0, A, B, cj, tbl, n0, d0, true);
            pair_dot(r1, A, B, cj, tbl, n1, d1, true);
        }
    } else {
        const int i0 = I * TI + tid;
        const int i1 = i0 + BLK;
        const int jbase = Jh * TJ;
        #pragma unroll 4
        for (int j = 0; j < TJ; ++j) {
            float4 A = sA[j];
            float4 B = sB[j];
            float cj = sC[j];
            const int jcol = jbase + j;
            pair_dot(r0, A, B, cj, tbl, n0, d0, jcol > i0);
            pair_dot(r1, A, B, cj, tbl, n1, d1, jcol > i1);
        }
    }

    float acc_num = fmaf(n0, cm0, n1 * cm1);
    float acc_den = fmaf(d0, cm0, d1 * cm1);

    #pragma unroll
    for (int o = 16; o > 0; o >>= 1) {
        acc_num += __shfl_xor_sync(0xFFFFFFFFu, acc_num, o);
        acc_den += __shfl_xor_sync(0xFFFFFFFFu, acc_den, o);
    }
    __shared__ float rn[BLK / 32], rd[BLK / 32];
    const int wid = tid >> 5;
    if ((tid & 31) == 0) { rn[wid] = acc_num; rd[wid] = acc_den; }
    __syncthreads();

    if (tid == 0) {
        float tn = rn[0] + rn[1] + rn[2] + rn[3];
        float td = rd[0] + rd[1] + rd[2] + rd[3];
        atomicAdd(&g_acc[2 * b + 0], (double)tn);
        atomicAdd(&g_acc[2 * b + 1], (double)td);
        __threadfence();
        int done = atomicAdd(&g_done, 1);
        if (done == TOTAL_CTAS - 1) {
            volatile double* acc = g_acc;
            double num0 = acc[0], den0 = acc[1], num1 = acc[2], den1 = acc[3];
            double e0 = 2.0 * den0; if (e0 < 1.0) e0 = 1.0;
            double e1 = 2.0 * den1; if (e1 < 1.0) e1 = 1.0;
            double l0 = (0.5 * num0) / e0;   // 2 * 0.25 * num / (2*den)
            double l1 = (0.5 * num1) / e1;
            out[0] = (float)(1.0 - 0.5 * (l0 + l1));
            acc[0] = 0.0; acc[1] = 0.0; acc[2] = 0.0; acc[3] = 0.0;
            g_done = 0;
            __threadfence();
        }
    }
}

extern "C" void kernel_launch(void* const* d_in, const int* in_sizes, int n_in,
                              void* d_out, int out_size) {
    const float* pred  = (const float*)d_in[0];
    const float* truec = (const float*)d_in[1];
    const int*   dna   = (const int*)d_in[2];
    const int*   rna   = (const int*)d_in[3];
    const int*   cm    = (const int*)d_in[4];

    lddt_fused<<<TOTAL_CTAS, BLK>>>(pred, truec, dna, rna, cm, (float*)d_out);
}

// round 16
// speedup vs baseline: 1.1813x; 1.0156x over previous
#include <cuda_runtime.h>
#include <cuda_bf16.h>

// SmoothLDDTLoss — b=2, n=4096. Single fused kernel.
// R13 base (dot-product distances, select mask, byte-offset baked 256-bin LUT,
// BLK=128, 256x32 tiles, IR=2, 2176 CTAs), hot-loop unroll 2.
// fminf clamp RESTORED: it is the NaN guard (sqrt.approx of a rounding-negative
// d^2 yields NaN; fminf(NaN,C)->C; NaN would otherwise survive fmaf(v,0,num)).

#define NTOK 4096
#define TJ 32
#define TI 256
#define BLK 128
#define NTILES_B 1088             // sum_{I=0}^{15} (128 - 8I)
#define TOTAL_CTAS (2 * NTILES_B)

#define TBL_N 256
#define TBL_H 0.0625f             // 16 / 256
#define DD_CLAMP 15.9375f         // 255 * H
#define MASK_BIG 2097152.0f       // 2^21 >> max cutoff^2 (900)

__device__ double g_acc[4];       // [num0, den0, num1, den1]
__device__ int g_done;

__device__ __forceinline__ float fsqrt_approx(float x) {
    float r; asm("sqrt.approx.f32 %0, %1;" : "=f"(r) : "f"(x)); return r;
}

// sum of 4 sigmoids sigma(t - x), t in {0.5,1,2,4}; rational: 1 exp + 1 div
__device__ __forceinline__ float sig4c(float x) {
    const float C0 = 0.60653066f, C1 = 0.36787944f, C2 = 0.13533528f, C3 = 0.018315639f;
    float e = __expf(x);
    float b0 = fmaf(e, C0, 1.0f), b1 = fmaf(e, C1, 1.0f);
    float b2 = fmaf(e, C2, 1.0f), b3 = fmaf(e, C3, 1.0f);
    float p01 = b0 * b1, p23 = b2 * b3;
    float numr = fmaf(b0 + b1, p23, (b2 + b3) * p01);
    return __fdividef(numr, p01 * p23);
}

struct RowS {
    float ax, ay, az, sp;   // -2*pred_i, |pred_i|^2
    float bx, by, bz, st;   // -2*true_i, |true_i|^2
    float nuc;              // 1 if nucleotide else 0
};

// one pair, dot-product form. A=(px,py,pz,|p|^2), B=(tx,ty,tz,|t|^2+maskbig), cj=675*wp_j
__device__ __forceinline__ void pair_dot(
    const RowS& r, float4 A, float4 B, float cj,
    const float2* __restrict__ tbl, float& num, float& den, bool active)
{
    float d2p = fmaf(r.ax, A.x, fmaf(r.ay, A.y, fmaf(r.az, A.z, r.sp))) + A.w;
    float d2t = fmaf(r.bx, B.x, fmaf(r.by, B.y, fmaf(r.bz, B.z, r.st))) + B.w;

    float cut2 = fmaf(r.nuc, cj, 225.0f);               // 225 or 900
    float mm = (d2t < cut2 && active) ? 1.0f : 0.0f;

    // fminf is the NaN guard: sqrt.approx(rounding-negative d2) -> NaN,
    // fminf(NaN, C) -> C. Do NOT remove.
    float dd = fminf(fabsf(fsqrt_approx(d2t) - fsqrt_approx(d2p)), DD_CLAMP);
    // direct float2 byte offset: (int(dd*16) & 255) * 8, via magic FFMA
    int boff = __float_as_int(fmaf(dd, 128.0f, 8388608.0f)) & 0x7F8;
    float2 e = *(const float2*)((const char*)tbl + boff);
    float v = fmaf(dd, e.y, e.x);                       // = 4 * eps

    num = fmaf(v, mm, num);
    den += mm;
}

__global__ void __launch_bounds__(BLK)
lddt_fused(const float* __restrict__ pred,
           const float* __restrict__ truec,
           const int* __restrict__ is_dna,
           const int* __restrict__ is_rna,
           const int* __restrict__ cmask,
           float* __restrict__ out)
{
    // decode (batch, I, Jh): i-row I (16 rows of 256) has 128 - 8I j-tiles
    int lin = blockIdx.x;
    const int b = (lin >= NTILES_B) ? 1 : 0;
    lin -= b * NTILES_B;
    int I = 0;
    {
        int cnt = 128;
        while (lin >= cnt) { lin -= cnt; I++; cnt -= 8; }
    }
    const int Jh = 8 * I + lin;
    const bool hot = (lin >= 8);

    const int tid = threadIdx.x;

    __shared__ float2 tbl[TBL_N];      // (v_k - k*s_k, s_k/H)
    __shared__ float vraw[TBL_N + 1];  // raw sig4 node values
    __shared__ float4 sA[TJ];          // pred xyz, |p|^2
    __shared__ float4 sB[TJ];          // true xyz, |t|^2 + (wt?0:BIG)
    __shared__ float  sC[TJ];          // 675 * wp_j

    for (int k = tid; k < TBL_N; k += BLK)
        vraw[k] = sig4c((float)k * TBL_H);
    if (tid == 0) vraw[TBL_N] = sig4c(16.0f);

    const int base = b * NTOK;

    if (tid < TJ) {
        const int jg = base + Jh * TJ + tid;
        float px = pred[3 * jg + 0], py = pred[3 * jg + 1], pz = pred[3 * jg + 2];
        float tx = truec[3 * jg + 0], ty = truec[3 * jg + 1], tz = truec[3 * jg + 2];
        float np = fmaf(px, px, fmaf(py, py, pz * pz));
        float nt = fmaf(tx, tx, fmaf(ty, ty, tz * tz));
        bool wt = (cmask[jg] != 0);
        sA[tid] = make_float4(px, py, pz, np);
        sB[tid] = make_float4(tx, ty, tz, wt ? nt : nt + MASK_BIG);
        sC[tid] = (is_dna[jg] != 0 || is_rna[jg] != 0) ? 675.0f : 0.0f;
    }
    __syncthreads();

    // bake (base, slope/H) per bin
    for (int k = tid; k < TBL_N; k += BLK) {
        float v0 = vraw[k];
        float s = vraw[k + 1] - v0;
        tbl[k] = make_float2(fmaf(-(float)k, s, v0), s * 16.0f);
    }

    // own rows: r0 = 256*I + tid, r1 = r0 + 128
    const int ig0 = base + I * TI + tid;
    const int ig1 = ig0 + BLK;
    RowS r0, r1;
    {
        float px = pred[3 * ig0 + 0], py = pred[3 * ig0 + 1], pz = pred[3 * ig0 + 2];
        float tx = truec[3 * ig0 + 0], ty = truec[3 * ig0 + 1], tz = truec[3 * ig0 + 2];
        r0.ax = -2.0f * px; r0.ay = -2.0f * py; r0.az = -2.0f * pz;
        r0.sp = fmaf(px, px, fmaf(py, py, pz * pz));
        r0.bx = -2.0f * tx; r0.by = -2.0f * ty; r0.bz = -2.0f * tz;
        r0.st = fmaf(tx, tx, fmaf(ty, ty, tz * tz));
        r0.nuc = (is_dna[ig0] != 0 || is_rna[ig0] != 0) ? 1.0f : 0.0f;
    }
    {
        float px = pred[3 * ig1 + 0], py = pred[3 * ig1 + 1], pz = pred[3 * ig1 + 2];
        float tx = truec[3 * ig1 + 0], ty = truec[3 * ig1 + 1], tz = truec[3 * ig1 + 2];
        r1.ax = -2.0f * px; r1.ay = -2.0f * py; r1.az = -2.0f * pz;
        r1.sp = fmaf(px, px, fmaf(py, py, pz * pz));
        r1.bx = -2.0f * tx; r1.by = -2.0f * ty; r1.bz = -2.0f * tz;
        r1.st = fmaf(tx, tx, fmaf(ty, ty, tz * tz));
        r1.nuc = (is_dna[ig1] != 0 || is_rna[ig1] != 0) ? 1.0f : 0.0f;
    }
    const float cm0 = (cmask[ig0] != 0) ? 1.0f : 0.0f;
    const float cm1 = (cmask[ig1] != 0) ? 1.0f : 0.0f;

    __syncthreads();

    float n0 = 0.0f, d0 = 0.0f, n1 = 0.0f, d1 = 0.0f;

    if (hot) {
        #pragma unroll 2
        for (int j = 0; j < TJ; ++j) {
            float4 A = sA[j];
            float4 B = sB[j];
            float cj = sC[j];
            pair_dot(r0, A, B, cj, tbl, n0, d0, true);
            pair_dot(r1, A, B, cj, tbl, n1, d1, true);
        }
    } else {
        const int i0 = I * TI + tid;
        const int i1 = i0 + BLK;
        const int jbase = Jh * TJ;
        #pragma unroll 2
        for (int j = 0; j < TJ; ++j) {
            float4 A = sA[j];
            float4 B = sB[j];
            float cj = sC[j];
            const int jcol = jbase + j;
            pair_dot(r0, A, B, cj, tbl, n0, d0, jcol > i0);
            pair_dot(r1, A, B, cj, tbl, n1, d1, jcol > i1);
        }
    }

    float acc_num = fmaf(n0, cm0, n1 * cm1);
    float acc_den = fmaf(d0, cm0, d1 * cm1);

    #pragma unroll
    for (int o = 16; o > 0; o >>= 1) {
        acc_num += __shfl_xor_sync(0xFFFFFFFFu, acc_num, o);
        acc_den += __shfl_xor_sync(0xFFFFFFFFu, acc_den, o);
    }
    __shared__ float rn[BLK / 32], rd[BLK / 32];
    const int wid = tid >> 5;
    if ((tid & 31) == 0) { rn[wid] = acc_num; rd[wid] = acc_den; }
    __syncthreads();

    if (tid == 0) {
        float tn = rn[0] + rn[1] + rn[2] + rn[3];
        float td = rd[0] + rd[1] + rd[2] + rd[3];
        atomicAdd(&g_acc[2 * b + 0], (double)tn);
        atomicAdd(&g_acc[2 * b + 1], (double)td);
        __threadfence();
        int done = atomicAdd(&g_done, 1);
        if (done == TOTAL_CTAS - 1) {
            volatile double* acc = g_acc;
            double num0 = acc[0], den0 = acc[1], num1 = acc[2], den1 = acc[3];
            double e0 = 2.0 * den0; if (e0 < 1.0) e0 = 1.0;
            double e1 = 2.0 * den1; if (e1 < 1.0) e1 = 1.0;
            double l0 = (0.5 * num0) / e0;   // 2 * 0.25 * num / (2*den)
            double l1 = (0.5 * num1) / e1;
            out[0] = (float)(1.0 - 0.5 * (l0 + l1));
            acc[0] = 0.0; acc[1] = 0.0; acc[2] = 0.0; acc[3] = 0.0;
            g_done = 0;
            __threadfence();
        }
    }
}

extern "C" void kernel_launch(void* const* d_in, const int* in_sizes, int n_in,
                              void* d_out, int out_size) {
    const float* pred  = (const float*)d_in[0];
    const float* truec = (const float*)d_in[1];
    const int*   dna   = (const int*)d_in[2];
    const int*   rna   = (const int*)d_in[3];
    const int*   cm    = (const int*)d_in[4];

    lddt_fused<<<TOTAL_CTAS, BLK>>>(pred, truec, dna, rna, cm, (float*)d_out);
}